// round 8
// baseline (speedup 1.0000x reference)
#include <cuda_runtime.h>
#include <cfloat>

// PoolingLayer: out[p, f] = max_k features[neighbor_indices[p, k], f]
// N=100000, NP=50000, K=32, F=128
// Inputs: points (N,3) f32 [unused], features (N,128) f32,
//         neighbor_indices (NP,32) int32. Output (NP,128) f32.
//
// LTS(L2)-bandwidth-bound random gather at ~17 TB/s effective. Winning
// config: one warp/point, lane = one float4 column, 4 rows in flight,
// ~43 regs / 56% occ. Streaming hints keep single-use idx/out data from
// evicting the L2-resident 51MB feature table (cuts DRAM refill traffic).

#define NPTS   100000
#define NP_OUT 50000
#define KNBR   32
#define FDIM   128            // 512 bytes per feature row

__device__ __forceinline__ float4 fmax4(float4 a, float4 b) {
    a.x = fmaxf(a.x, b.x);
    a.y = fmaxf(a.y, b.y);
    a.z = fmaxf(a.z, b.z);
    a.w = fmaxf(a.w, b.w);
    return a;
}

__global__ __launch_bounds__(256)
void pool_max_kernel(const char* __restrict__ feats_b,   // features base (bytes)
                     const int* __restrict__ nbr,        // (NP, 32) int32
                     float4* __restrict__ out)            // (NP, 32) float4
{
    const int gtid = blockIdx.x * blockDim.x + threadIdx.x;
    const int warp = gtid >> 5;          // one warp per output point
    const int lane = gtid & 31;          // one float4 column per lane
    if (warp >= NP_OUT) return;

    // Coalesced, streaming (evict-first) load of the 32 neighbor indices,
    // pre-scaled to a row byte offset.
    const int my_idx = __ldcs(nbr + (size_t)warp * KNBR + lane);
    const int my_off = my_idx << 9;                // *512 bytes per row

    const char* base = feats_b + (lane << 4);      // fold lane column offset once

    const float4 NEG = make_float4(-FLT_MAX, -FLT_MAX, -FLT_MAX, -FLT_MAX);
    float4 acc0 = NEG, acc1 = NEG, acc2 = NEG, acc3 = NEG;

    // 32 neighbors, 4 loads in flight, 4 independent max chains.
    #pragma unroll
    for (int k = 0; k < KNBR; k += 4) {
        const int o0 = __shfl_sync(0xffffffffu, my_off, k + 0);
        const int o1 = __shfl_sync(0xffffffffu, my_off, k + 1);
        const int o2 = __shfl_sync(0xffffffffu, my_off, k + 2);
        const int o3 = __shfl_sync(0xffffffffu, my_off, k + 3);
        float4 v0 = *reinterpret_cast<const float4*>(base + o0);
        float4 v1 = *reinterpret_cast<const float4*>(base + o1);
        float4 v2 = *reinterpret_cast<const float4*>(base + o2);
        float4 v3 = *reinterpret_cast<const float4*>(base + o3);
        acc0 = fmax4(acc0, v0);
        acc1 = fmax4(acc1, v1);
        acc2 = fmax4(acc2, v2);
        acc3 = fmax4(acc3, v3);
    }

    acc0 = fmax4(acc0, acc1);
    acc2 = fmax4(acc2, acc3);
    acc0 = fmax4(acc0, acc2);

    // Streaming store: single-use output, keep it out of L2's way.
    __stcs(out + (size_t)warp * (FDIM / 4) + lane, acc0);
}

extern "C" void kernel_launch(void* const* d_in, const int* in_sizes, int n_in,
                              void* d_out, int out_size) {
    // d_in[0] = points (unused), d_in[1] = features, d_in[2] = neighbor_indices
    const char* feats = (const char*)d_in[1];
    const int* nbr = (const int*)d_in[2];
    float4* out = (float4*)d_out;

    const int total_threads = NP_OUT * 32;      // one warp per output point
    const int block = 256;
    const int grid = (total_threads + block - 1) / block;
    pool_max_kernel<<<grid, block>>>(feats, nbr, out);
}

// round 9
// speedup vs baseline: 1.0305x; 1.0305x over previous
#include <cuda_runtime.h>
#include <cfloat>

// PoolingLayer: out[p, f] = max_k features[neighbor_indices[p, k], f]
// N=100000, NP=50000, K=32, F=128
// Inputs: points (N,3) f32 [unused], features (N,128) f32,
//         neighbor_indices (NP,32) int32. Output (NP,128) f32.
//
// LTS(L2)-bandwidth-bound random gather (~850MB through L2, table is
// L2-resident). One warp per point, lane = one float4 column, 4 rows in
// flight. Indices are staged in smem as pre-scaled byte offsets and read
// back as int4 LDS.128 broadcasts -- replaces 32 SHFLs/warp (MIO pressure,
// serial offset chain) with 8 broadcast LDS.

#define NPTS   100000
#define NP_OUT 50000
#define KNBR   32
#define FDIM   128            // 512 bytes per feature row
#define WARPS_PER_BLOCK 8

__device__ __forceinline__ float4 fmax4(float4 a, float4 b) {
    a.x = fmaxf(a.x, b.x);
    a.y = fmaxf(a.y, b.y);
    a.z = fmaxf(a.z, b.z);
    a.w = fmaxf(a.w, b.w);
    return a;
}

__global__ __launch_bounds__(256)
void pool_max_kernel(const char* __restrict__ feats_b,   // features base (bytes)
                     const int* __restrict__ nbr,        // (NP, 32) int32
                     float4* __restrict__ out)            // (NP, 32) float4
{
    __shared__ int4 soff[WARPS_PER_BLOCK * (KNBR / 4)];  // 8 pts x 32 offsets

    const int tid  = threadIdx.x;
    const int wib  = tid >> 5;                 // warp in block = point in block
    const int lane = tid & 31;
    const int point = blockIdx.x * WARPS_PER_BLOCK + wib;

    // Stage all 8x32 indices for this block: one coalesced load per thread,
    // pre-scaled to row byte offsets (idx*512).
    {
        const size_t idx_base = (size_t)blockIdx.x * (WARPS_PER_BLOCK * KNBR);
        int v = nbr[idx_base + tid];
        ((int*)soff)[tid] = v << 9;
    }
    __syncthreads();

    if (point >= NP_OUT) return;

    const char* base = feats_b + (lane << 4);  // fold lane column offset once

    const float4 NEG = make_float4(-FLT_MAX, -FLT_MAX, -FLT_MAX, -FLT_MAX);
    float4 acc0 = NEG, acc1 = NEG, acc2 = NEG, acc3 = NEG;

    // 32 neighbors: per batch, one broadcast LDS.128 yields 4 offsets;
    // 4 gather loads in flight, 4 independent max chains.
    #pragma unroll
    for (int k = 0; k < KNBR / 4; k++) {
        const int4 o = soff[wib * (KNBR / 4) + k];   // warp-uniform -> broadcast
        float4 v0 = *reinterpret_cast<const float4*>(base + o.x);
        float4 v1 = *reinterpret_cast<const float4*>(base + o.y);
        float4 v2 = *reinterpret_cast<const float4*>(base + o.z);
        float4 v3 = *reinterpret_cast<const float4*>(base + o.w);
        acc0 = fmax4(acc0, v0);
        acc1 = fmax4(acc1, v1);
        acc2 = fmax4(acc2, v2);
        acc3 = fmax4(acc3, v3);
    }

    acc0 = fmax4(acc0, acc1);
    acc2 = fmax4(acc2, acc3);
    acc0 = fmax4(acc0, acc2);

    out[(size_t)point * (FDIM / 4) + lane] = acc0;
}

extern "C" void kernel_launch(void* const* d_in, const int* in_sizes, int n_in,
                              void* d_out, int out_size) {
    // d_in[0] = points (unused), d_in[1] = features, d_in[2] = neighbor_indices
    const char* feats = (const char*)d_in[1];
    const int* nbr = (const int*)d_in[2];
    float4* out = (float4*)d_out;

    const int block = 256;                       // 8 warps = 8 points
    const int grid = (NP_OUT + WARPS_PER_BLOCK - 1) / WARPS_PER_BLOCK;
    pool_max_kernel<<<grid, block>>>(feats, nbr, out);
}

// round 10
// speedup vs baseline: 1.0450x; 1.0141x over previous
#include <cuda_runtime.h>
#include <cfloat>

// PoolingLayer: out[p, f] = max_k features[neighbor_indices[p, k], f]
// N=100000, NP=50000, K=32, F=128
// Inputs: points (N,3) f32 [unused], features (N,128) f32,
//         neighbor_indices (NP,32) int32. Output (NP,128) f32.
//
// LTS-bound random gather. This round: Blackwell 256-bit vector loads.
// One warp per point; lane covers a 32-byte (8-float) slot; 16 lanes span a
// 512B feature row, so ONE ld.global.v8 fetches TWO neighbor rows (lower
// half-warp row k, upper half-warp row k+1). Halves gather LDG count and
// store count vs the float4 version; cross-half max via shfl_xor(16).

#define NPTS   100000
#define NP_OUT 50000
#define KNBR   32
#define FDIM   128            // 512 bytes per feature row

__device__ __forceinline__ void ldg256(const char* p, float* v) {
    asm volatile("ld.global.v8.f32 {%0,%1,%2,%3,%4,%5,%6,%7}, [%8];"
                 : "=f"(v[0]), "=f"(v[1]), "=f"(v[2]), "=f"(v[3]),
                   "=f"(v[4]), "=f"(v[5]), "=f"(v[6]), "=f"(v[7])
                 : "l"(p));
}

__device__ __forceinline__ void stg256(char* p, const float* v) {
    asm volatile("st.global.v8.f32 [%0], {%1,%2,%3,%4,%5,%6,%7,%8};"
                 :: "l"(p),
                    "f"(v[0]), "f"(v[1]), "f"(v[2]), "f"(v[3]),
                    "f"(v[4]), "f"(v[5]), "f"(v[6]), "f"(v[7])
                 : "memory");
}

__global__ __launch_bounds__(256)
void pool_max_kernel(const char* __restrict__ feats_b,   // features base (bytes)
                     const int* __restrict__ nbr,        // (NP, 32) int32
                     char* __restrict__ out_b)            // (NP, 128) f32 (bytes)
{
    const int gtid = blockIdx.x * blockDim.x + threadIdx.x;
    const int warp = gtid >> 5;          // one warp per output point
    const int lane = gtid & 31;
    if (warp >= NP_OUT) return;

    const int half = lane >> 4;          // 0: even rows, 1: odd rows
    const int m    = lane & 15;          // 32-byte slot within the row

    // Coalesced load of the 32 neighbor indices, pre-scaled to byte offsets.
    const int my_idx = nbr[(size_t)warp * KNBR + lane];
    const int my_off = my_idx << 9;      // *512 bytes per row

    const char* base = feats_b + (m << 5);   // + slot*32 bytes

    float acc[8];
    #pragma unroll
    for (int j = 0; j < 8; j++) acc[j] = -FLT_MAX;

    // 32 neighbors, 4 rows per batch via 2 LDG.256 in flight.
    #pragma unroll
    for (int k = 0; k < KNBR; k += 4) {
        const int oA = __shfl_sync(0xffffffffu, my_off, k + half);      // rows k / k+1
        const int oB = __shfl_sync(0xffffffffu, my_off, k + 2 + half);  // rows k+2 / k+3
        float va[8], vb[8];
        ldg256(base + oA, va);
        ldg256(base + oB, vb);
        #pragma unroll
        for (int j = 0; j < 8; j++)
            acc[j] = fmaxf(acc[j], fmaxf(va[j], vb[j]));
    }

    // Combine lower-half (even rows) with upper-half (odd rows): same column
    // slot lives in lane m and lane m+16.
    #pragma unroll
    for (int j = 0; j < 8; j++) {
        const float o = __shfl_xor_sync(0xffffffffu, acc[j], 16);
        acc[j] = fmaxf(acc[j], o);
    }

    // Lanes 0..15 write the 512B output row with STG.256.
    if (half == 0) {
        stg256(out_b + (size_t)warp * (FDIM * 4) + (m << 5), acc);
    }
}

extern "C" void kernel_launch(void* const* d_in, const int* in_sizes, int n_in,
                              void* d_out, int out_size) {
    // d_in[0] = points (unused), d_in[1] = features, d_in[2] = neighbor_indices
    const char* feats = (const char*)d_in[1];
    const int* nbr = (const int*)d_in[2];
    char* out = (char*)d_out;

    const int total_threads = NP_OUT * 32;      // one warp per output point
    const int block = 256;
    const int grid = (total_threads + block - 1) / block;
    pool_max_kernel<<<grid, block>>>(feats, nbr, out);
}